// round 15
// baseline (speedup 1.0000x reference)
#include <cuda_runtime.h>

#define NQ       12
#define DIM      4096            // 2^12
#define NLAYERS  6
#define NGATES   (NLAYERS * NQ)  // 72
#define THREADS  128
#define APT      (DIM / THREADS) // 32 amplitudes per thread

typedef unsigned long long ull;

// Bank-conflict-avoiding layout: amplitude p lives at sAmp[SWZ(p)].
// GF(2)-linear and invertible: SWZ(a^b) = SWZ(a)^SWZ(b).
#define SWZ(p) ((p) ^ (((p) >> 4) & 0xFu))

// GF(2) matrices of the CNOT-chain map per layer (verified: rowA.colB = I,
// leading bit of cCOLB[l][q] is q). cROWA[l][j] = row j of T^l; cCOLB = col of T^-l.
__constant__ unsigned cROWA[NLAYERS + 1][NQ] = {
    {0x001,0x002,0x004,0x008,0x010,0x020,0x040,0x080,0x100,0x200,0x400,0x800},
    {0xFFF,0xFFE,0xFFC,0xFF8,0xFF0,0xFE0,0xFC0,0xF80,0xF00,0xE00,0xC00,0x800},
    {0x555,0xAAA,0x554,0xAA8,0x550,0xAA0,0x540,0xA80,0x500,0xA00,0x400,0x800},
    {0x333,0x666,0xCCC,0x998,0x330,0x660,0xCC0,0x980,0x300,0x600,0xC00,0x800},
    {0x111,0x222,0x444,0x888,0x110,0x220,0x440,0x880,0x100,0x200,0x400,0x800},
    {0xF0F,0xE1E,0xC3C,0x878,0x0F0,0x1E0,0x3C0,0x780,0xF00,0xE00,0xC00,0x800},
    {0x505,0xA0A,0x414,0x828,0x050,0x0A0,0x140,0x280,0x500,0xA00,0x400,0x800},
};
__constant__ unsigned cCOLB[NLAYERS][NQ] = {
    {0x001,0x002,0x004,0x008,0x010,0x020,0x040,0x080,0x100,0x200,0x400,0x800},
    {0x001,0x003,0x006,0x00C,0x018,0x030,0x060,0x0C0,0x180,0x300,0x600,0xC00},
    {0x001,0x002,0x005,0x00A,0x014,0x028,0x050,0x0A0,0x140,0x280,0x500,0xA00},
    {0x001,0x003,0x007,0x00F,0x01E,0x03C,0x078,0x0F0,0x1E0,0x3C0,0x780,0xF00},
    {0x001,0x002,0x004,0x008,0x011,0x022,0x044,0x088,0x110,0x220,0x440,0x880},
    {0x001,0x003,0x006,0x00C,0x019,0x033,0x066,0x0CC,0x198,0x330,0x660,0xCC0},
};

// Z-sign masks in physical space: cROWA[6][11-q] for q = 0..11 (hard constants).
__constant__ unsigned cZMASK[NQ] = {
    0x800,0x400,0xA00,0x500,0x280,0x140,0x0A0,0x050,0x828,0x414,0xA0A,0x505
};

// ---- packed f32x2 primitives (Blackwell FFMA2 path) ----
__device__ __forceinline__ ull f2mul(ull a, ull b) {
    ull d; asm("mul.rn.f32x2 %0, %1, %2;" : "=l"(d) : "l"(a), "l"(b)); return d;
}
__device__ __forceinline__ ull f2fma(ull a, ull b, ull c) {
    ull d; asm("fma.rn.f32x2 %0, %1, %2, %3;" : "=l"(d) : "l"(a), "l"(b), "l"(c)); return d;
}
__device__ __forceinline__ ull f2swap(ull v) {  // (re,im) -> (im,re)
    ull d;
    asm("{\n\t.reg .b32 lo, hi;\n\tmov.b64 {lo, hi}, %1;\n\tmov.b64 %0, {hi, lo};\n\t}"
        : "=l"(d) : "l"(v));
    return d;
}
__device__ __forceinline__ ull packf2(float lo, float hi) {
    return (ull)__float_as_uint(lo) | ((ull)__float_as_uint(hi) << 32);
}
__device__ __forceinline__ void unpk2(ull v, float& lo, float& hi) {
    asm("mov.b64 {%0, %1}, %2;" : "=f"(lo), "=f"(hi) : "l"(v));
}

// One complex 2x2 butterfly on packed (re,im) amplitudes.
// Exploits Rot symmetry: G11 = conj(G00), G10 = -conj(G01).
__device__ __forceinline__ void bf(ull& x0, ull& x1,
                                   ull r0, ull im, ull rm, ull i1v,
                                   ull ra, ull ia) {
    ull s0 = f2swap(x0), s1 = f2swap(x1);
    ull o0 = f2mul(r0, x0);
    o0 = f2fma(im,  s0, o0);
    o0 = f2fma(rm,  x1, o0);
    o0 = f2fma(i1v, s1, o0);
    ull o1 = f2mul(ra, x0);
    o1 = f2fma(i1v, s0, o1);
    o1 = f2fma(r0,  x1, o1);
    o1 = f2fma(ia,  s1, o1);
    x0 = o0; x1 = o1;
}

// Apply the 4 fused gates of one pass to v[16] (coeff base g6, parities c*).
__device__ __forceinline__ void apply4(ull* v, const ull* __restrict__ sGateP,
                                       int g6, unsigned cA, unsigned cB,
                                       unsigned cC, unsigned cD) {
    {   // gate A (group bit 3); orientation via index shifts on 6-word table
        ull r0 = sGateP[g6 + 0],        im = sGateP[g6 + 1 + cA];
        ull ia = sGateP[g6 + 2 - cA],   rm = sGateP[g6 + 3 + cA];
        ull ra = sGateP[g6 + 4 - cA],   i1 = sGateP[g6 + 5];
        #pragma unroll
        for (int k = 0; k < 8; k++)
            bf(v[k], v[k + 8], r0, im, rm, i1, ra, ia);
    }
    {   // gate B (group bit 2)
        const int gb = g6 + 6;
        ull r0 = sGateP[gb + 0],        im = sGateP[gb + 1 + cB];
        ull ia = sGateP[gb + 2 - cB],   rm = sGateP[gb + 3 + cB];
        ull ra = sGateP[gb + 4 - cB],   i1 = sGateP[gb + 5];
        #pragma unroll
        for (int h = 0; h < 16; h += 8)
            #pragma unroll
            for (int k = 0; k < 4; k++)
                bf(v[h + k], v[h + k + 4], r0, im, rm, i1, ra, ia);
    }
    {   // gate C (group bit 1)
        const int gb = g6 + 12;
        ull r0 = sGateP[gb + 0],        im = sGateP[gb + 1 + cC];
        ull ia = sGateP[gb + 2 - cC],   rm = sGateP[gb + 3 + cC];
        ull ra = sGateP[gb + 4 - cC],   i1 = sGateP[gb + 5];
        #pragma unroll
        for (int h = 0; h < 16; h += 4)
            #pragma unroll
            for (int k = 0; k < 2; k++)
                bf(v[h + k], v[h + k + 2], r0, im, rm, i1, ra, ia);
    }
    {   // gate D (group bit 0)
        const int gb = g6 + 18;
        ull r0 = sGateP[gb + 0],        im = sGateP[gb + 1 + cD];
        ull ia = sGateP[gb + 2 - cD],   rm = sGateP[gb + 3 + cD];
        ull ra = sGateP[gb + 4 - cD],   i1 = sGateP[gb + 5];
        #pragma unroll
        for (int k = 0; k < 16; k += 2)
            bf(v[k], v[k + 1], r0, im, rm, i1, ra, ia);
    }
}

__global__ __launch_bounds__(THREADS, 6)
void qsim_kernel(const float* __restrict__ x,
                 const float* __restrict__ params,
                 float* __restrict__ out) {
    __shared__ ull    sAmp[DIM];            // 32 KB statevector, packed (re,im), swizzled
    __shared__ ull    sGateP[NGATES * 6];   // 3.4 KB: {r0, i0, i0s, r1, r1n, i1} per gate
    __shared__ float  sc[NQ], ssn[NQ];      // cos(x/2), sin(x/2)
    __shared__ float2 sMf[16], sLf[16];     // product tables: qubits 4..7 / 8..11
    __shared__ ull    sT4r[16], sT4i[16];   // packed coeffs: qubits 0..3 product
    __shared__ float  sExp[NQ];             // <Z_q> accumulators

    const int tid = threadIdx.x;
    const int b   = blockIdx.x;

    // ---- stage 0: trig + compressed packed gate table ----
    if (tid < NQ) {
        float xv = x[b * NQ + tid];
        sc[tid]   = cosf(0.5f * xv);
        ssn[tid]  = sinf(0.5f * xv);
        sExp[tid] = 0.0f;
    }
    if (tid < NGATES) {
        float phi = params[tid * 3 + 0];
        float th  = params[tid * 3 + 1];
        float om  = params[tid * 3 + 2];
        float ct = cosf(0.5f * th), st = sinf(0.5f * th);
        float aa = 0.5f * (phi + om), bb = 0.5f * (phi - om);
        float ca = cosf(aa), sa = sinf(aa);
        float cb = cosf(bb), sb = sinf(bb);
        // G00 = (gr0, gi0) = (ca ct, -sa ct); G01 = (gr1, gi1) = (-cb st, -sb st)
        // G10 = -conj(G01); G11 = conj(G00)
        float gr0 = ca * ct, gi0 = -sa * ct;
        float gr1 = -cb * st, gi1 = -sb * st;
        int tb = tid * 6;
        sGateP[tb + 0] = packf2( gr0,  gr0);   // r0
        sGateP[tb + 1] = packf2(-gi0,  gi0);   // i0
        sGateP[tb + 2] = packf2( gi0, -gi0);   // i0s = swap(i0)  (i-coef of G11)
        sGateP[tb + 3] = packf2( gr1,  gr1);   // r1
        sGateP[tb + 4] = packf2(-gr1, -gr1);   // r1n (real of G10)
        sGateP[tb + 5] = packf2(-gi1,  gi1);   // i1  (i-coef of G01 and G10)
    }
    __syncthreads();

    // ---- stage 1: three 16-entry RX product tables ----
    // index idx: bit (3-j) of idx = occupation of the j-th qubit in the block
    if (tid < 16) {
        float2 m = make_float2(1.0f, 0.0f);   // qubits 4..7
        float2 w = make_float2(1.0f, 0.0f);   // qubits 8..11
        float2 t = make_float2(1.0f, 0.0f);   // qubits 0..3
        #pragma unroll
        for (int j = 0; j < 4; j++) {
            int bit = (tid >> (3 - j)) & 1;
            int qm = 4 + j, qw = 8 + j, qt = j;
            m = bit ? make_float2(m.y * ssn[qm], -m.x * ssn[qm])
                    : make_float2(m.x * sc[qm],   m.y * sc[qm]);
            w = bit ? make_float2(w.y * ssn[qw], -w.x * ssn[qw])
                    : make_float2(w.x * sc[qw],   w.y * sc[qw]);
            t = bit ? make_float2(t.y * ssn[qt], -t.x * ssn[qt])
                    : make_float2(t.x * sc[qt],   t.y * sc[qt]);
        }
        sMf[tid] = m;
        sLf[tid] = w;
        sT4r[tid] = packf2( t.x, t.x);
        sT4i[tid] = packf2(-t.y, t.y);
    }
    __syncthreads();

    // ---- stage 2: init fused with first gate pass (l=0, qp=0) ----
    // Masks are identity bits {0x800,0x400,0x200,0x100} (SWZ-invariant),
    // rep < 256 so all orientation parities are 0.
    {
        #pragma unroll
        for (int it = 0; it < DIM / 16 / THREADS; it++) {
            unsigned g  = tid + it * THREADS;     // = rep (pb=8, hi bits 0)
            unsigned sb = SWZ(g);
            float2 m = sMf[(g >> 4) & 15], w = sLf[g & 15];
            ull basep = packf2(fmaf(m.x, w.x, -m.y * w.y),
                               fmaf(m.x, w.y,  m.y * w.x));
            ull bsw = f2swap(basep);
            ull v[16];
            #pragma unroll
            for (int k = 0; k < 16; k++)
                v[k] = f2fma(sT4r[k], basep, f2mul(sT4i[k], bsw));
            apply4(v, sGateP, 0, 0u, 0u, 0u, 0u);
            #pragma unroll
            for (int k = 0; k < 16; k++) {
                unsigned off = ((k & 8) ? 0x800u : 0u) ^ ((k & 4) ? 0x400u : 0u)
                             ^ ((k & 2) ? 0x200u : 0u) ^ ((k & 1) ? 0x100u : 0u);
                sAmp[sb ^ off] = v[k];
            }
        }
        __syncthreads();
    }

    // ---- stage 3: remaining passes; first (0,0) and last (5,8) handled elsewhere ----
    for (int l = 0; l < NLAYERS; l++) {
        #pragma unroll
        for (int qp = 0; qp < NQ; qp += 4) {
            if (l == 0 && qp == 0) continue;             // fused with init
            if (l == NLAYERS - 1 && qp == 8) continue;   // fused with measurement
            const int jA = 11 - qp;
            const int pb = 8 - qp;                 // pivot block low bit: 8,4,0
            const unsigned rA = cROWA[l][jA],     rB = cROWA[l][jA - 1];
            const unsigned rC = cROWA[l][jA - 2], rD = cROWA[l][jA - 3];
            const unsigned wA = SWZ(cCOLB[l][jA]),     wB = SWZ(cCOLB[l][jA - 1]);
            const unsigned wC = SWZ(cCOLB[l][jA - 2]), wD = SWZ(cCOLB[l][jA - 3]);
            const unsigned lomask = (pb > 0) ? ((1u << pb) - 1u) : 0u;
            const int g6 = (l * NQ + qp) * 6;      // compressed-coeff base (gate A)

            #pragma unroll
            for (int it = 0; it < DIM / 16 / THREADS; it++) {  // 2 groups/thread
                unsigned g   = tid + it * THREADS;             // 8-bit coset id
                unsigned rep = ((g >> pb) << (pb + 4)) | (g & lomask);
                const unsigned sb = SWZ(rep);
                const unsigned cA = __popc(rA & rep) & 1u;
                const unsigned cB = __popc(rB & rep) & 1u;
                const unsigned cC = __popc(rC & rep) & 1u;
                const unsigned cD = __popc(rD & rep) & 1u;

                ull v[16];
                #pragma unroll
                for (int k = 0; k < 16; k++) {
                    unsigned off = ((k & 8) ? wA : 0u) ^ ((k & 4) ? wB : 0u)
                                 ^ ((k & 2) ? wC : 0u) ^ ((k & 1) ? wD : 0u);
                    v[k] = sAmp[sb ^ off];
                }
                apply4(v, sGateP, g6, cA, cB, cC, cD);
                #pragma unroll
                for (int k = 0; k < 16; k++) {
                    unsigned off = ((k & 8) ? wA : 0u) ^ ((k & 4) ? wB : 0u)
                                 ^ ((k & 2) ? wC : 0u) ^ ((k & 1) ? wD : 0u);
                    sAmp[sb ^ off] = v[k];
                }
            }
            __syncthreads();
        }
    }

    // ---- stage 4: final pass (l=5, qp=8) fused with measurement ----
    // e_q = (-1)^parity(cZMASK[q] & rep) * W[t(q)], W = 16-pt WHT of group probs;
    // t(q) = 0 for q<8; 8,12,14,15 for q = 8,9,10,11 (derived from T).
    {
        const int l = NLAYERS - 1, qp = 8;
        const int jA = 11 - qp;                    // 3
        const unsigned rA = cROWA[l][jA],     rB = cROWA[l][jA - 1];
        const unsigned rC = cROWA[l][jA - 2], rD = cROWA[l][jA - 3];
        const unsigned wA = SWZ(cCOLB[l][jA]),     wB = SWZ(cCOLB[l][jA - 1]);
        const unsigned wC = SWZ(cCOLB[l][jA - 2]), wD = SWZ(cCOLB[l][jA - 3]);
        const int g6 = (l * NQ + qp) * 6;

        float e[NQ];
        #pragma unroll
        for (int q = 0; q < NQ; q++) e[q] = 0.0f;

        #pragma unroll
        for (int it = 0; it < DIM / 16 / THREADS; it++) {
            unsigned g   = tid + it * THREADS;
            unsigned rep = g << 4;                 // pb = 0
            const unsigned sb = SWZ(rep);
            const unsigned cA = __popc(rA & rep) & 1u;
            const unsigned cB = __popc(rB & rep) & 1u;
            const unsigned cC = __popc(rC & rep) & 1u;
            const unsigned cD = __popc(rD & rep) & 1u;

            ull v[16];
            #pragma unroll
            for (int k = 0; k < 16; k++) {
                unsigned off = ((k & 8) ? wA : 0u) ^ ((k & 4) ? wB : 0u)
                             ^ ((k & 2) ? wC : 0u) ^ ((k & 1) ? wD : 0u);
                v[k] = sAmp[sb ^ off];
            }
            apply4(v, sGateP, g6, cA, cB, cC, cD);

            // probabilities (no store-back needed)
            float w[16];
            #pragma unroll
            for (int k = 0; k < 16; k++) {
                ull pp = f2mul(v[k], v[k]);
                float lo, hi; unpk2(pp, lo, hi);
                w[k] = lo + hi;
            }
            // 16-point WHT: W[t] = sum_k (-1)^popc(k&t) p_k
            #pragma unroll
            for (int s = 1; s < 16; s <<= 1) {
                #pragma unroll
                for (int k = 0; k < 16; k++) {
                    if (!(k & s)) {
                        float a0 = w[k], a1 = w[k | s];
                        w[k] = a0 + a1;
                        w[k | s] = a0 - a1;
                    }
                }
            }
            // accumulate e_q with compile-time WHT indices
            const int TI[NQ] = {0,0,0,0,0,0,0,0,8,12,14,15};
            #pragma unroll
            for (int q = 0; q < NQ; q++) {
                float val = w[TI[q]];
                e[q] += (__popc(cZMASK[q] & rep) & 1) ? -val : val;
            }
        }

        #pragma unroll
        for (int q = 0; q < NQ; q++) {
            float v2 = e[q];
            #pragma unroll
            for (int off = 16; off > 0; off >>= 1)
                v2 += __shfl_down_sync(0xffffffffu, v2, off);
            if ((tid & 31) == 0) atomicAdd(&sExp[q], v2);
        }
    }
    __syncthreads();

    // ---- stage 5: readout mitigation, closed form ----
    // M = J - I => M^-1 = J/(n-1) - I ; out_q = (E+12)/11 - e_q - 2
    if (tid < NQ) {
        float E = 0.0f;
        #pragma unroll
        for (int q = 0; q < NQ; q++) E += sExp[q];
        out[b * NQ + tid] = (E + 12.0f) * (1.0f / 11.0f) - sExp[tid] - 2.0f;
    }
}

extern "C" void kernel_launch(void* const* d_in, const int* in_sizes, int n_in,
                              void* d_out, int out_size) {
    const float* x      = (const float*)d_in[0];
    const float* params = (const float*)d_in[1];
    if (n_in >= 2 && in_sizes[0] == NLAYERS * NQ * 3) {
        x      = (const float*)d_in[1];
        params = (const float*)d_in[0];
    }
    cudaFuncSetAttribute(qsim_kernel,
                         cudaFuncAttributePreferredSharedMemoryCarveout, 100);
    int nblk = out_size / NQ;   // 768
    qsim_kernel<<<nblk, THREADS>>>(x, params, (float*)d_out);
}

// round 16
// speedup vs baseline: 1.0579x; 1.0579x over previous
#include <cuda_runtime.h>

#define NQ       12
#define DIM      4096            // 2^12
#define NLAYERS  6
#define NGATES   (NLAYERS * NQ)  // 72
#define THREADS  128
#define APT      (DIM / THREADS) // 32 amplitudes per thread

typedef unsigned long long ull;

// Bank-conflict-avoiding layout: amplitude p lives at sAmp[SWZ(p)].
// GF(2)-linear and invertible: SWZ(a^b) = SWZ(a)^SWZ(b).
#define SWZ(p) ((p) ^ (((p) >> 4) & 0xFu))

// GF(2) matrices of the CNOT-chain map per layer (verified: rowA.colB = I,
// leading bit of cCOLB[l][q] is q). cROWA[l][j] = row j of T^l; cCOLB = col of T^-l.
__constant__ unsigned cROWA[NLAYERS + 1][NQ] = {
    {0x001,0x002,0x004,0x008,0x010,0x020,0x040,0x080,0x100,0x200,0x400,0x800},
    {0xFFF,0xFFE,0xFFC,0xFF8,0xFF0,0xFE0,0xFC0,0xF80,0xF00,0xE00,0xC00,0x800},
    {0x555,0xAAA,0x554,0xAA8,0x550,0xAA0,0x540,0xA80,0x500,0xA00,0x400,0x800},
    {0x333,0x666,0xCCC,0x998,0x330,0x660,0xCC0,0x980,0x300,0x600,0xC00,0x800},
    {0x111,0x222,0x444,0x888,0x110,0x220,0x440,0x880,0x100,0x200,0x400,0x800},
    {0xF0F,0xE1E,0xC3C,0x878,0x0F0,0x1E0,0x3C0,0x780,0xF00,0xE00,0xC00,0x800},
    {0x505,0xA0A,0x414,0x828,0x050,0x0A0,0x140,0x280,0x500,0xA00,0x400,0x800},
};
__constant__ unsigned cCOLB[NLAYERS][NQ] = {
    {0x001,0x002,0x004,0x008,0x010,0x020,0x040,0x080,0x100,0x200,0x400,0x800},
    {0x001,0x003,0x006,0x00C,0x018,0x030,0x060,0x0C0,0x180,0x300,0x600,0xC00},
    {0x001,0x002,0x005,0x00A,0x014,0x028,0x050,0x0A0,0x140,0x280,0x500,0xA00},
    {0x001,0x003,0x007,0x00F,0x01E,0x03C,0x078,0x0F0,0x1E0,0x3C0,0x780,0xF00},
    {0x001,0x002,0x004,0x008,0x011,0x022,0x044,0x088,0x110,0x220,0x440,0x880},
    {0x001,0x003,0x006,0x00C,0x019,0x033,0x066,0x0CC,0x198,0x330,0x660,0xCC0},
};

// Z-sign masks in physical space: cROWA[6][11-q] for q = 0..11 (hard constants).
__constant__ unsigned cZMASK[NQ] = {
    0x800,0x400,0xA00,0x500,0x280,0x140,0x0A0,0x050,0x828,0x414,0xA0A,0x505
};

// ---- packed f32x2 primitives (Blackwell FFMA2 path) ----
__device__ __forceinline__ ull f2mul(ull a, ull b) {
    ull d; asm("mul.rn.f32x2 %0, %1, %2;" : "=l"(d) : "l"(a), "l"(b)); return d;
}
__device__ __forceinline__ ull f2fma(ull a, ull b, ull c) {
    ull d; asm("fma.rn.f32x2 %0, %1, %2, %3;" : "=l"(d) : "l"(a), "l"(b), "l"(c)); return d;
}
__device__ __forceinline__ ull f2swap(ull v) {  // (re,im) -> (im,re)
    ull d;
    asm("{\n\t.reg .b32 lo, hi;\n\tmov.b64 {lo, hi}, %1;\n\tmov.b64 %0, {hi, lo};\n\t}"
        : "=l"(d) : "l"(v));
    return d;
}
__device__ __forceinline__ ull packf2(float lo, float hi) {
    return (ull)__float_as_uint(lo) | ((ull)__float_as_uint(hi) << 32);
}
__device__ __forceinline__ void unpk2(ull v, float& lo, float& hi) {
    asm("mov.b64 {%0, %1}, %2;" : "=f"(lo), "=f"(hi) : "l"(v));
}

// One complex 2x2 butterfly on packed (re,im) amplitudes.
// Exploits Rot symmetry: G11 = conj(G00), G10 = -conj(G01).
__device__ __forceinline__ void bf(ull& x0, ull& x1,
                                   ull r0, ull im, ull rm, ull i1v,
                                   ull ra, ull ia) {
    ull s0 = f2swap(x0), s1 = f2swap(x1);
    ull o0 = f2mul(r0, x0);
    o0 = f2fma(im,  s0, o0);
    o0 = f2fma(rm,  x1, o0);
    o0 = f2fma(i1v, s1, o0);
    ull o1 = f2mul(ra, x0);
    o1 = f2fma(i1v, s0, o1);
    o1 = f2fma(r0,  x1, o1);
    o1 = f2fma(ia,  s1, o1);
    x0 = o0; x1 = o1;
}

// Apply the 4 fused gates of one pass to v[16] (coeff base g6, parities c*).
__device__ __forceinline__ void apply4(ull* v, const ull* __restrict__ sGateP,
                                       int g6, unsigned cA, unsigned cB,
                                       unsigned cC, unsigned cD) {
    {   // gate A (group bit 3); orientation via index shifts on 6-word table
        ull r0 = sGateP[g6 + 0],        im = sGateP[g6 + 1 + cA];
        ull ia = sGateP[g6 + 2 - cA],   rm = sGateP[g6 + 3 + cA];
        ull ra = sGateP[g6 + 4 - cA],   i1 = sGateP[g6 + 5];
        #pragma unroll
        for (int k = 0; k < 8; k++)
            bf(v[k], v[k + 8], r0, im, rm, i1, ra, ia);
    }
    {   // gate B (group bit 2)
        const int gb = g6 + 6;
        ull r0 = sGateP[gb + 0],        im = sGateP[gb + 1 + cB];
        ull ia = sGateP[gb + 2 - cB],   rm = sGateP[gb + 3 + cB];
        ull ra = sGateP[gb + 4 - cB],   i1 = sGateP[gb + 5];
        #pragma unroll
        for (int h = 0; h < 16; h += 8)
            #pragma unroll
            for (int k = 0; k < 4; k++)
                bf(v[h + k], v[h + k + 4], r0, im, rm, i1, ra, ia);
    }
    {   // gate C (group bit 1)
        const int gb = g6 + 12;
        ull r0 = sGateP[gb + 0],        im = sGateP[gb + 1 + cC];
        ull ia = sGateP[gb + 2 - cC],   rm = sGateP[gb + 3 + cC];
        ull ra = sGateP[gb + 4 - cC],   i1 = sGateP[gb + 5];
        #pragma unroll
        for (int h = 0; h < 16; h += 4)
            #pragma unroll
            for (int k = 0; k < 2; k++)
                bf(v[h + k], v[h + k + 2], r0, im, rm, i1, ra, ia);
    }
    {   // gate D (group bit 0)
        const int gb = g6 + 18;
        ull r0 = sGateP[gb + 0],        im = sGateP[gb + 1 + cD];
        ull ia = sGateP[gb + 2 - cD],   rm = sGateP[gb + 3 + cD];
        ull ra = sGateP[gb + 4 - cD],   i1 = sGateP[gb + 5];
        #pragma unroll
        for (int k = 0; k < 16; k += 2)
            bf(v[k], v[k + 1], r0, im, rm, i1, ra, ia);
    }
}

// One full gate pass over the statevector (2 groups/thread). No sync inside.
__device__ __forceinline__ void gate_pass(ull* __restrict__ sAmp,
                                          const ull* __restrict__ sGateP,
                                          int l, int qp, int pb, int tid) {
    const int jA = 11 - qp;
    const unsigned rA = cROWA[l][jA],     rB = cROWA[l][jA - 1];
    const unsigned rC = cROWA[l][jA - 2], rD = cROWA[l][jA - 3];
    const unsigned wA = SWZ(cCOLB[l][jA]),     wB = SWZ(cCOLB[l][jA - 1]);
    const unsigned wC = SWZ(cCOLB[l][jA - 2]), wD = SWZ(cCOLB[l][jA - 3]);
    const unsigned lomask = (pb > 0) ? ((1u << pb) - 1u) : 0u;
    const int g6 = (l * NQ + qp) * 6;

    #pragma unroll
    for (int it = 0; it < DIM / 16 / THREADS; it++) {   // 2 groups/thread
        unsigned g   = tid + it * THREADS;              // 8-bit coset id
        unsigned rep = ((g >> pb) << (pb + 4)) | (g & lomask);
        const unsigned sb = SWZ(rep);
        const unsigned cA = __popc(rA & rep) & 1u;
        const unsigned cB = __popc(rB & rep) & 1u;
        const unsigned cC = __popc(rC & rep) & 1u;
        const unsigned cD = __popc(rD & rep) & 1u;

        ull v[16];
        #pragma unroll
        for (int k = 0; k < 16; k++) {
            unsigned off = ((k & 8) ? wA : 0u) ^ ((k & 4) ? wB : 0u)
                         ^ ((k & 2) ? wC : 0u) ^ ((k & 1) ? wD : 0u);
            v[k] = sAmp[sb ^ off];
        }
        apply4(v, sGateP, g6, cA, cB, cC, cD);
        #pragma unroll
        for (int k = 0; k < 16; k++) {
            unsigned off = ((k & 8) ? wA : 0u) ^ ((k & 4) ? wB : 0u)
                         ^ ((k & 2) ? wC : 0u) ^ ((k & 1) ? wD : 0u);
            sAmp[sb ^ off] = v[k];
        }
    }
}

__global__ __launch_bounds__(THREADS, 6)
void qsim_kernel(const float* __restrict__ x,
                 const float* __restrict__ params,
                 float* __restrict__ out) {
    __shared__ ull    sAmp[DIM];            // 32 KB statevector, packed (re,im), swizzled
    __shared__ ull    sGateP[NGATES * 6];   // 3.4 KB: {r0, i0, i0s, r1, r1n, i1} per gate
    __shared__ float  sc[NQ], ssn[NQ];      // cos(x/2), sin(x/2)
    __shared__ float2 sL[32];               // product table, qubits 7..11
    __shared__ float  sExp[NQ];             // <Z_q> accumulators

    float2* sAmpF = reinterpret_cast<float2*>(sAmp);

    const int tid = threadIdx.x;
    const int b   = blockIdx.x;

    // ---- stage 0: trig + compressed packed gate table ----
    if (tid < NQ) {
        float xv = x[b * NQ + tid];
        sc[tid]   = cosf(0.5f * xv);
        ssn[tid]  = sinf(0.5f * xv);
        sExp[tid] = 0.0f;
    }
    if (tid < NGATES) {
        float phi = params[tid * 3 + 0];
        float th  = params[tid * 3 + 1];
        float om  = params[tid * 3 + 2];
        float ct = cosf(0.5f * th), st = sinf(0.5f * th);
        float aa = 0.5f * (phi + om), bb = 0.5f * (phi - om);
        float ca = cosf(aa), sa = sinf(aa);
        float cb = cosf(bb), sb = sinf(bb);
        // G00 = (gr0, gi0) = (ca ct, -sa ct); G01 = (gr1, gi1) = (-cb st, -sb st)
        // G10 = -conj(G01); G11 = conj(G00)
        float gr0 = ca * ct, gi0 = -sa * ct;
        float gr1 = -cb * st, gi1 = -sb * st;
        int tb = tid * 6;
        sGateP[tb + 0] = packf2( gr0,  gr0);   // r0
        sGateP[tb + 1] = packf2(-gi0,  gi0);   // i0
        sGateP[tb + 2] = packf2( gi0, -gi0);   // i0s = swap(i0)  (i-coef of G11)
        sGateP[tb + 3] = packf2( gr1,  gr1);   // r1
        sGateP[tb + 4] = packf2(-gr1, -gr1);   // r1n (real of G10)
        sGateP[tb + 5] = packf2(-gi1,  gi1);   // i1  (i-coef of G01 and G10)
    }
    __syncthreads();

    // ---- stage 1: low-5-bit product table (qubits 7..11 <-> bits 4..0) ----
    if (tid < 32) {
        float2 v = make_float2(1.0f, 0.0f);
        #pragma unroll
        for (int j = 0; j < 5; j++) {
            int q   = 7 + j;
            int bit = (tid >> (4 - j)) & 1;
            v = bit ? make_float2(v.y * ssn[q], -v.x * ssn[q])  // v * (-i sin)
                    : make_float2(v.x * sc[q],   v.y * sc[q]);  // v * cos
        }
        sL[tid] = v;
    }
    __syncthreads();

    // ---- stage 2: direct product-state init (RX embedding on |0..0>) ----
    {
        float2 h = make_float2(1.0f, 0.0f);
        #pragma unroll
        for (int j = 0; j < 7; j++) {
            int bit = (tid >> (6 - j)) & 1;
            h = bit ? make_float2(h.y * ssn[j], -h.x * ssn[j])
                    : make_float2(h.x * sc[j],   h.y * sc[j]);
        }
        #pragma unroll
        for (int lo = 0; lo < 32; lo++) {
            unsigned p = tid * APT + lo;
            float2 g = sL[lo];
            float2 r = make_float2(fmaf(h.x, g.x, -h.y * g.y),
                                   fmaf(h.x, g.y,  h.y * g.x));
            sAmpF[SWZ(p)] = r;
        }
    }
    __syncthreads();

    // ---- stage 3: variational layers. Per layer: qp=0 (full barrier),
    //      qp=4 -> qp=8 are TILE-CLOSED PER WARP (addr bits 11..8 fixed and
    //      identical warp ownership in both passes; masks have support <= bit 7
    //      resp. bit 3) so only a __syncwarp is needed between them. ----
    for (int l = 0; l < NLAYERS; l++) {
        gate_pass(sAmp, sGateP, l, 0, 8, tid);
        __syncthreads();
        gate_pass(sAmp, sGateP, l, 4, 4, tid);
        __syncwarp();
        if (l < NLAYERS - 1) {
            gate_pass(sAmp, sGateP, l, 8, 0, tid);
            __syncthreads();
        }
    }

    // ---- stage 4: final pass (l=5, qp=8) fused with measurement ----
    // e_q = (-1)^parity(cZMASK[q] & rep) * W[t(q)], W = 16-pt WHT of group probs;
    // t(q) = 0 for q<8; 8,12,14,15 for q = 8,9,10,11 (derived from T).
    {
        const int l = NLAYERS - 1, qp = 8;
        const int jA = 11 - qp;                    // 3
        const unsigned rA = cROWA[l][jA],     rB = cROWA[l][jA - 1];
        const unsigned rC = cROWA[l][jA - 2], rD = cROWA[l][jA - 3];
        const unsigned wA = SWZ(cCOLB[l][jA]),     wB = SWZ(cCOLB[l][jA - 1]);
        const unsigned wC = SWZ(cCOLB[l][jA - 2]), wD = SWZ(cCOLB[l][jA - 3]);
        const int g6 = (l * NQ + qp) * 6;

        float e[NQ];
        #pragma unroll
        for (int q = 0; q < NQ; q++) e[q] = 0.0f;

        #pragma unroll
        for (int it = 0; it < DIM / 16 / THREADS; it++) {
            unsigned g   = tid + it * THREADS;
            unsigned rep = g << 4;                 // pb = 0
            const unsigned sb = SWZ(rep);
            const unsigned cA = __popc(rA & rep) & 1u;
            const unsigned cB = __popc(rB & rep) & 1u;
            const unsigned cC = __popc(rC & rep) & 1u;
            const unsigned cD = __popc(rD & rep) & 1u;

            ull v[16];
            #pragma unroll
            for (int k = 0; k < 16; k++) {
                unsigned off = ((k & 8) ? wA : 0u) ^ ((k & 4) ? wB : 0u)
                             ^ ((k & 2) ? wC : 0u) ^ ((k & 1) ? wD : 0u);
                v[k] = sAmp[sb ^ off];
            }
            apply4(v, sGateP, g6, cA, cB, cC, cD);

            // probabilities (no store-back needed)
            float w[16];
            #pragma unroll
            for (int k = 0; k < 16; k++) {
                ull pp = f2mul(v[k], v[k]);
                float lo, hi; unpk2(pp, lo, hi);
                w[k] = lo + hi;
            }
            // 16-point WHT: W[t] = sum_k (-1)^popc(k&t) p_k
            #pragma unroll
            for (int s = 1; s < 16; s <<= 1) {
                #pragma unroll
                for (int k = 0; k < 16; k++) {
                    if (!(k & s)) {
                        float a0 = w[k], a1 = w[k | s];
                        w[k] = a0 + a1;
                        w[k | s] = a0 - a1;
                    }
                }
            }
            // accumulate e_q with compile-time WHT indices
            const int TI[NQ] = {0,0,0,0,0,0,0,0,8,12,14,15};
            #pragma unroll
            for (int q = 0; q < NQ; q++) {
                float val = w[TI[q]];
                e[q] += (__popc(cZMASK[q] & rep) & 1) ? -val : val;
            }
        }

        #pragma unroll
        for (int q = 0; q < NQ; q++) {
            float v2 = e[q];
            #pragma unroll
            for (int off = 16; off > 0; off >>= 1)
                v2 += __shfl_down_sync(0xffffffffu, v2, off);
            if ((tid & 31) == 0) atomicAdd(&sExp[q], v2);
        }
    }
    __syncthreads();

    // ---- stage 5: readout mitigation, closed form ----
    // M = J - I => M^-1 = J/(n-1) - I ; out_q = (E+12)/11 - e_q - 2
    if (tid < NQ) {
        float E = 0.0f;
        #pragma unroll
        for (int q = 0; q < NQ; q++) E += sExp[q];
        out[b * NQ + tid] = (E + 12.0f) * (1.0f / 11.0f) - sExp[tid] - 2.0f;
    }
}

extern "C" void kernel_launch(void* const* d_in, const int* in_sizes, int n_in,
                              void* d_out, int out_size) {
    const float* x      = (const float*)d_in[0];
    const float* params = (const float*)d_in[1];
    if (n_in >= 2 && in_sizes[0] == NLAYERS * NQ * 3) {
        x      = (const float*)d_in[1];
        params = (const float*)d_in[0];
    }
    cudaFuncSetAttribute(qsim_kernel,
                         cudaFuncAttributePreferredSharedMemoryCarveout, 100);
    int nblk = out_size / NQ;   // 768
    qsim_kernel<<<nblk, THREADS>>>(x, params, (float*)d_out);
}